// round 17
// baseline (speedup 1.0000x reference)
#include <cuda_runtime.h>
#include <cuda_fp16.h>
#include <cstdint>

#define PP 32      // num networks
#define HH 128     // hidden
#define BB 32      // batch
#define TT 256     // seq len
#define NTHREADS 256
#define KTILES 10  // K = 160 = 10 x 16
#define NB 8       // batches per CTA

// B buffer: 8 batch-rows x PADW words (u32 = packed f16 k-pair).
// PADW=90 -> row stride 360 B, conflict-free for fragment loads.
#define PADW 90
#define BBUF (NB * PADW * 4)             // 2880 per buffer

// smem byte offsets
#define OFF_BIAS 0                        // 4*128 f32 = 2048
#define OFF_WOUT 2048                     // 128 f32 = 512
#define OFF_B0   2560                     // 2 buffers x BBUF = 5760
#define SMEM_BYTES (OFF_B0 + 2 * BBUF)    // 8320

// packed X scratch: [b][t][16 words], each word = f16 k-pair
__device__ uint32_t Xp_g[BB * TT * 16];

__device__ __forceinline__ __half2 tanh2(__half2 x) {
    uint32_t xx = *reinterpret_cast<uint32_t*>(&x);
    asm("tanh.approx.f16x2 %0, %1;" : "=r"(xx) : "r"(xx));
    return *reinterpret_cast<__half2*>(&xx);
}
__device__ __forceinline__ __half2 sig2(__half2 x) {
    const __half2 h05 = __floats2half2_rn(0.5f, 0.5f);
    return __hfma2(tanh2(__hmul2(x, h05)), h05, h05);
}

__device__ __forceinline__ uint32_t pack_h2(float lo_k, float hi_k) {
    __half a = __float2half_rn(lo_k);
    __half b = __float2half_rn(hi_k);
    return (uint32_t)__half_as_ushort(a) | ((uint32_t)__half_as_ushort(b) << 16);
}

__device__ __forceinline__ void mma16816(float* d, const uint32_t* a, uint32_t b0, uint32_t b1) {
    asm volatile(
        "mma.sync.aligned.m16n8k16.row.col.f32.f16.f16.f32 "
        "{%0,%1,%2,%3}, {%4,%5,%6,%7}, {%8,%9}, {%0,%1,%2,%3};"
        : "+f"(d[0]), "+f"(d[1]), "+f"(d[2]), "+f"(d[3])
        : "r"(a[0]), "r"(a[1]), "r"(a[2]), "r"(a[3]), "r"(b0), "r"(b1));
}

__global__ void init_out_kernel(float* __restrict__ out, const float* __restrict__ b_out) {
    int i = blockIdx.x * blockDim.x + threadIdx.x;
    if (i < BB * TT * PP) out[i] = b_out[i & (PP - 1)];
}

// pack X into f16 word layout: word w of (b,t) holds k-pair at
// d0 = (w>>3)*16 + ((w&7)>>1)*2 + (w&1)*8
__global__ void xsplit_kernel(const float* __restrict__ X) {
    int i = blockIdx.x * blockDim.x + threadIdx.x;
    if (i >= BB * TT * 16) return;
    int w = i & 15;
    int bt = i >> 4;              // b*TT + t
    int d0 = ((w >> 3) * 16) + (((w & 7) >> 1) * 2) + ((w & 1) * 8);
    float v0 = X[(size_t)bt * PP + d0];
    float v1 = X[(size_t)bt * PP + d0 + 1];
    Xp_g[i] = pack_h2(v0, v1);
}

extern __shared__ char smem_c[];

__global__ void __launch_bounds__(NTHREADS, 1)
clstm_mma_kernel(const float* __restrict__ Wih,
                 const float* __restrict__ Whh,
                 const float* __restrict__ bih,
                 const float* __restrict__ bhh,
                 const float* __restrict__ Wout,
                 float* __restrict__ out)
{
    const int tid  = threadIdx.x;
    const int lane = tid & 31;
    const int wid  = tid >> 5;           // 8 warps; warp owns j in [wid*16, wid*16+16)
    const int r    = lane >> 2;          // fragment row group (0..7)
    const int tg   = lane & 3;           // fragment thread-in-group

    const int n  = blockIdx.x >> 2;      // network id
    const int bg = blockIdx.x & 3;       // batch group: global b = bg*8 + blocal
    const int j1 = wid * 16 + r;         // this thread's first j
    const int j2 = j1 + 8;               // second j

    // ---- zero both B buffers (h region must start at 0) ----
    {
        uint4 z = make_uint4(0, 0, 0, 0);
        for (int i = tid; i < 2 * BBUF / 16; i += NTHREADS)
            reinterpret_cast<uint4*>(smem_c + OFF_B0)[i] = z;
    }

    // ---- bias + wout for all 128 j ----
    for (int idx = tid; idx < 4 * HH; idx += NTHREADS) {
        int g = idx >> 7, j = idx & 127;
        int row = n * 4 * HH + g * HH + j;
        *reinterpret_cast<float*>(smem_c + OFF_BIAS + idx * 4) = bih[row] + bhh[row];
    }
    for (int idx = tid; idx < HH; idx += NTHREADS)
        *reinterpret_cast<float*>(smem_c + OFF_WOUT + idx * 4) = Wout[n * HH + idx];

    // ---- load A fragments (f16) into registers ----
    // m-tile mt = gate mt; tile rows 0..7 -> j1, rows 8..15 -> j2.
    uint32_t Ah[4][KTILES][4];
#pragma unroll
    for (int mt = 0; mt < 4; ++mt) {
        const size_t grow1 = (size_t)(n * 4 * HH + mt * HH + j1);
        const size_t grow2 = (size_t)(n * 4 * HH + mt * HH + j2);
#pragma unroll
        for (int kt = 0; kt < KTILES; ++kt) {
#pragma unroll
            for (int e = 0; e < 4; ++e) {
                // e: 0 -> (j1, k0), 1 -> (j2, k0), 2 -> (j1, k0+8), 3 -> (j2, k0+8)
                size_t grow = (e & 1) ? grow2 : grow1;
                int k = kt * 16 + tg * 2 + ((e >> 1) * 8);
                float v0, v1;
                if (k < PP) {
                    v0 = Wih[grow * PP + k];
                    v1 = Wih[grow * PP + k + 1];
                } else {
                    v0 = Whh[grow * HH + (k - PP)];
                    v1 = Whh[grow * HH + (k - PP) + 1];
                }
                Ah[mt][kt][e] = pack_h2(v0, v1);
            }
        }
    }

    // ordering: zero/bias/wout writes before X staging & reads
    __syncthreads();

    // ---- stage X(t=0) into buffer 0 (threads 0..63) ----
    const int xbl = tid >> 3;            // batch local 0..7 (valid for tid<64)
    const int xwp = (tid & 7) * 2;
    const int xbg = bg * NB + xbl;       // global batch
    if (tid < 64) {
        uint2 v = *reinterpret_cast<const uint2*>(&Xp_g[((size_t)xbg * TT + 0) * 16 + xwp]);
        *reinterpret_cast<uint2*>(smem_c + OFF_B0 + (xbl * PADW + xwp) * 4) = v;
    }

    // per-thread epilogue constants
    const float biasI1 = *reinterpret_cast<float*>(smem_c + OFF_BIAS + (0 * HH + j1) * 4);
    const float biasF1 = *reinterpret_cast<float*>(smem_c + OFF_BIAS + (1 * HH + j1) * 4);
    const float biasG1 = *reinterpret_cast<float*>(smem_c + OFF_BIAS + (2 * HH + j1) * 4);
    const float biasO1 = *reinterpret_cast<float*>(smem_c + OFF_BIAS + (3 * HH + j1) * 4);
    const float biasI2 = *reinterpret_cast<float*>(smem_c + OFF_BIAS + (0 * HH + j2) * 4);
    const float biasF2 = *reinterpret_cast<float*>(smem_c + OFF_BIAS + (1 * HH + j2) * 4);
    const float biasG2 = *reinterpret_cast<float*>(smem_c + OFF_BIAS + (2 * HH + j2) * 4);
    const float biasO2 = *reinterpret_cast<float*>(smem_c + OFF_BIAS + (3 * HH + j2) * 4);
    const float wout1  = *reinterpret_cast<float*>(smem_c + OFF_WOUT + j1 * 4);
    const float wout2  = *reinterpret_cast<float*>(smem_c + OFF_WOUT + j2 * 4);

    // h-write word offsets for j-pairs (even r packs (j, j+1)); k = 32 + j
    const int khe1 = PP + (j1 & ~1);
    const int khe2 = PP + (j2 & ~1);
    const uint32_t hw1 = (uint32_t)((khe1 >> 4) * 8 + ((khe1 >> 1) & 3) * 2 + ((khe1 >> 3) & 1)) * 4;
    const uint32_t hw2 = (uint32_t)((khe2 >> 4) * 8 + ((khe2 >> 1) & 3) * 2 + ((khe2 >> 3) & 1)) * 4;

    // cell state: idx = jj*2 + cc -> (j = jj?j2:j1, b = tg*2+cc)
    float c[4] = {0.0f, 0.0f, 0.0f, 0.0f};

    __syncthreads();

    for (int t = 0; t < TT; ++t) {
        const char* bufp = smem_c + OFF_B0 + (t & 1) * BBUF;
        const uint32_t offB_next = (uint32_t)(OFF_B0 + ((t & 1) ^ 1) * BBUF);

        // prefetch X(t+1)
        int tn = (t + 1 < TT) ? (t + 1) : t;
        uint2 pv;
        if (tid < 64)
            pv = *reinterpret_cast<const uint2*>(&Xp_g[((size_t)xbg * TT + tn) * 16 + xwp]);

        // ---- plain f16 GEMM: 4 m-tiles x 10 k-tiles ----
        float acc[4][4];
#pragma unroll
        for (int mt = 0; mt < 4; ++mt)
#pragma unroll
            for (int e = 0; e < 4; ++e) acc[mt][e] = 0.0f;

#pragma unroll
        for (int kt = 0; kt < KTILES; ++kt) {
            uint32_t boff = (uint32_t)(r * PADW + kt * 8 + tg * 2) * 4;
            uint2 bh = *reinterpret_cast<const uint2*>(bufp + boff);
#pragma unroll
            for (int mt = 0; mt < 4; ++mt) mma16816(acc[mt], Ah[mt][kt], bh.x, bh.y);
        }

        // ---- fused epilogue: half2 activations (tanh.approx.f16x2), c in fp32 ----
        float pb0 = 0.0f, pb1 = 0.0f;    // head partials for b = tg*2, tg*2+1
#pragma unroll
        for (int jj = 0; jj < 2; ++jj) {
            const float bI = jj ? biasI2 : biasI1;
            const float bF = jj ? biasF2 : biasF1;
            const float bG = jj ? biasG2 : biasG1;
            const float bO = jj ? biasO2 : biasO1;
            const float wo = jj ? wout2 : wout1;
            const uint32_t hw = jj ? hw2 : hw1;
            const int idx0 = jj * 2, idx1 = jj * 2 + 1;

            // fp32 bias add, then pack batch-pairs into half2 (low = cc0)
            __half2 i2 = sig2(__floats2half2_rn(acc[0][idx0] + bI, acc[0][idx1] + bI));
            __half2 f2 = sig2(__floats2half2_rn(acc[1][idx0] + bF, acc[1][idx1] + bF));
            __half2 g2 = tanh2(__floats2half2_rn(acc[2][idx0] + bG, acc[2][idx1] + bG));
            __half2 o2 = sig2(__floats2half2_rn(acc[3][idx0] + bO, acc[3][idx1] + bO));

            // cell update in fp32
            float nc0 = fmaf(__low2float(f2),  c[idx0], __low2float(i2)  * __low2float(g2));
            float nc1 = fmaf(__high2float(f2), c[idx1], __high2float(i2) * __high2float(g2));
            c[idx0] = nc0;
            c[idx1] = nc1;

            __half2 tc2 = tanh2(__floats2half2_rn(nc0, nc1));
            __half2 h2v = __hmul2(o2, tc2);          // h already in f16, both cc packed

            // head partials in fp32
            pb0 = fmaf(__low2float(h2v),  wo, pb0);
            pb1 = fmaf(__high2float(h2v), wo, pb1);

            // pack (j, j+1) across lanes: partner j+1 lives at lane+4
            uint32_t myh = *reinterpret_cast<uint32_t*>(&h2v);
            uint32_t thh = __shfl_down_sync(0xffffffffu, myh, 4);
            if (!(r & 1)) {
                uint32_t w0, w1;
                asm("prmt.b32 %0, %1, %2, 0x5410;" : "=r"(w0) : "r"(myh), "r"(thh)); // cc0: {h(j+1) lo, h(j) lo}
                asm("prmt.b32 %0, %1, %2, 0x7632;" : "=r"(w1) : "r"(myh), "r"(thh)); // cc1: hi halves
                uint32_t row0 = (uint32_t)(tg * 2 + 0) * (PADW * 4);
                uint32_t row1 = (uint32_t)(tg * 2 + 1) * (PADW * 4);
                *reinterpret_cast<uint32_t*>(smem_c + offB_next + row0 + hw) = w0;
                *reinterpret_cast<uint32_t*>(smem_c + offB_next + row1 + hw) = w1;
            }
        }

        // ---- stage X(t+1) into next buffer ----
        if (tid < 64)
            *reinterpret_cast<uint2*>(smem_c + offB_next + (xbl * PADW + xwp) * 4) = pv;

        // head: reduce over the warp's 16 j's (r axis: lane bits 2,3,4)
        pb0 += __shfl_xor_sync(0xffffffffu, pb0, 4);
        pb0 += __shfl_xor_sync(0xffffffffu, pb0, 8);
        pb0 += __shfl_xor_sync(0xffffffffu, pb0, 16);
        pb1 += __shfl_xor_sync(0xffffffffu, pb1, 4);
        pb1 += __shfl_xor_sync(0xffffffffu, pb1, 8);
        pb1 += __shfl_xor_sync(0xffffffffu, pb1, 16);
        if (r == 0) {
            int b0g = bg * NB + tg * 2;
            atomicAdd(&out[((size_t)b0g * TT + t) * PP + n], pb0);
            atomicAdd(&out[((size_t)(b0g + 1) * TT + t) * PP + n], pb1);
        }

        // order this step's h/X stores before next step's B loads
        __syncthreads();
    }
}

extern "C" void kernel_launch(void* const* d_in, const int* in_sizes, int n_in,
                              void* d_out, int out_size) {
    const float* X    = (const float*)d_in[0];
    const float* Wih  = (const float*)d_in[1];
    const float* Whh  = (const float*)d_in[2];
    const float* bih  = (const float*)d_in[3];
    const float* bhh  = (const float*)d_in[4];
    const float* Wout = (const float*)d_in[5];
    const float* bout = (const float*)d_in[6];
    float* out = (float*)d_out;

    cudaFuncSetAttribute(clstm_mma_kernel, cudaFuncAttributeMaxDynamicSharedMemorySize, SMEM_BYTES);

    init_out_kernel<<<(BB * TT * PP + 255) / 256, 256>>>(out, bout);
    xsplit_kernel<<<(BB * TT * 16 + 255) / 256, 256>>>(X);
    clstm_mma_kernel<<<PP * 4, NTHREADS, SMEM_BYTES>>>(Wih, Whh, bih, bhh, Wout, out);
}